// round 14
// baseline (speedup 1.0000x reference)
#include <cuda_runtime.h>
#include <stdint.h>

// Cl(8,0,0): 256 comps, 1024 multivectors (4x256), out [3,1024,256].
// 4x4 XOR tiling on bits 6,7 (R11/R12) + R14: per-u sign pre-XORed into the
// 4 A-rows (alu pipe), so geometric-product accumulation is add.rn.f32x2
// (2 distinct u64 operands -> RF-bank rt=2 instead of FMA2's rt=3).
// Wedge/inner keep FMA2 with pure 0/1.0 mask coefficients.
// G=4 batch elems, 128-thr blocks (32 iL x 4 j-slices), grid 512.

#define NCOMP 256
#define G 4
#define BATCH_ELEMS 1024

typedef unsigned long long u64;

#define MUL2(out, a, b) \
    asm("mul.rn.f32x2 %0, %1, %2;" : "=l"(out) : "l"(a), "l"(b))
#define FMA2(out, a, b, c) \
    asm("fma.rn.f32x2 %0, %1, %2, %3;" : "=l"(out) : "l"(a), "l"(b), "l"(c))
#define ADD2(out, a, b) \
    asm("add.rn.f32x2 %0, %1, %2;" : "=l"(out) : "l"(a), "l"(b))

__device__ __forceinline__ u64 pack2(unsigned w) {
    u64 r;
    asm("mov.b64 %0, {%1, %1};" : "=l"(r) : "r"(w));
    return r;
}
__device__ __forceinline__ float2 unpack2(u64 v) {
    float2 f;
    asm("mov.b64 {%0, %1}, %2;" : "=f"(f.x), "=f"(f.y) : "l"(v));
    return f;
}

__host__ __device__ __forceinline__ constexpr unsigned ppf(unsigned v) {
    unsigned x = v << 1;
    x ^= x << 1;
    x ^= x << 2;
    x ^= x << 4;
    return x & 0xffu;
}

__device__ __forceinline__ unsigned submask16(unsigned m) {
    unsigned w = 1u;
    if (m & 1u) w |= w << 1;
    if (m & 2u) w |= w << 2;
    if (m & 4u) w |= w << 4;
    if (m & 8u) w |= w << 8;
    return w;
}
__device__ __forceinline__ unsigned supmask16(unsigned r) {
    unsigned w = 0xFFFFu;
    if (r & 1u) w &= 0xAAAAu;
    if (r & 2u) w &= 0xCCCCu;
    if (r & 4u) w &= 0xF0F0u;
    if (r & 8u) w &= 0xFF00u;
    return w;
}

// smem: phase 1: sA (4096B) + sB (4096B); phase 2 (aliased): 64*25 u64 = 12800B
#define SMEM_BYTES 12800
#define RSTRIDE 25

__global__ __launch_bounds__(128, 4) void clifford_kernel(
    const float* __restrict__ A,
    const float* __restrict__ B,
    float* __restrict__ out) {
    __shared__ __align__(16) char smem_raw[SMEM_BYTES];
    float* sA = (float*)smem_raw;             // [j*4 + g], (-1)^q(j) folded in
    float* sB = (float*)(smem_raw + 4096);    // [k*4 + g], 16B rows

    const int tid = threadIdx.x;              // 0..127
    const int s = tid >> 5;                   // j-slice 0..3 (one per warp)
    const int iq = blockIdx.x & 1;
    const int iL = iq * 32 + (tid & 31);      // base i (bits 6,7 = 0)
    const int base = (blockIdx.x >> 1) * G;

    // Coalesced fill; fold (-1)^{q(j)} into A
    #pragma unroll
    for (int r = 0; r < (NCOMP * G) / 128; ++r) {
        int idx = r * 128 + tid;
        int j = idx & (NCOMP - 1);
        int g = idx >> 8;
        float a = A[(base + g) * NCOMP + j];
        unsigned q = (unsigned)__popc(j & (int)ppf((unsigned)j)) & 1u;
        sA[j * 4 + g] = __int_as_float(__float_as_int(a) ^ (int)(q << 31));
        sB[j * 4 + g] = B[(base + g) * NCOMP + j];
    }
    __syncthreads();

    const int i = iL;
    const unsigned pp_i = ppf((unsigned)i);
    const unsigned par_i = (unsigned)__popc(i) & 1u;
    const u64 pis2 = pack2(par_i << 31);
    const u64 neg2 = 0x8000000080000000ULL;

    unsigned lut_s = 0u;                      // bit u = parity(u & pp_i)
    if (pp_i & 1u) lut_s ^= 0xAAAAu;
    if (pp_i & 2u) lut_s ^= 0xCCCCu;
    if (pp_i & 4u) lut_s ^= 0xF0F0u;
    if (pp_i & 8u) lut_s ^= 0xFF00u;

    const int jo = s << 4;                    // bits 4,5 of j
    const unsigned pjo = (unsigned)__popc(jo & (int)pp_i) & 1u;
    const unsigned S_w = pjo ? (lut_s ^ 0xFFFFu) : lut_s;
    const unsigned W_w = (((jo & ~i) & 0x30) == 0) ? submask16((unsigned)i & 15u) : 0u;
    const unsigned C1_w = (((jo & i) & 0x30) == 0) ? submask16((unsigned)(~i) & 15u) : 0u;
    const unsigned C2_w = (((i & ~jo) & 0x30) == 0) ? supmask16((unsigned)i & 15u) : 0u;
    const int koi = jo ^ i;

    u64 Gm[4][2], Wm[4][2], Nm[4][2];
    #pragma unroll
    for (int m = 0; m < 4; ++m)
        #pragma unroll
        for (int p = 0; p < 2; ++p) { Gm[m][p] = 0ull; Wm[m][p] = 0ull; Nm[m][p] = 0ull; }

    #pragma unroll
    for (int u = 0; u < 16; ++u) {            // u compile-time
        const int j = jo | u;
        const int k = koi ^ u;
        // sign bit for this u (applied to A rows via XOR, alu pipe)
        const unsigned sb = (S_w << (31 - u)) & 0x80000000u;
        const u64 sb2 = pack2(sb);
        const u64 f1 = sb2 ^ pis2;            // a1/a2 combined folds
        const u64 f3 = sb2 ^ neg2;            // a3 fold
        // masks as 0 / +1.0f coefficient pairs (sign already in products)
        const unsigned wm = (unsigned)(((int)(W_w << (31 - u))) >> 31);
        const unsigned c1m = (unsigned)(((int)(C1_w << (31 - u))) >> 31);
        const unsigned c2m = (unsigned)(((int)(C2_w << (31 - u))) >> 31);
        const u64 w2 = pack2(wm & 0x3f800000u);
        const u64 n1 = pack2(c1m & 0x3f800000u);
        const u64 n2 = pack2(c2m & 0x3f800000u);
        const u64 n12 = pack2((c1m | c2m) & 0x3f800000u);

        const ulonglong2 A0 = *(const ulonglong2*)(sA + j * 4);
        const ulonglong2 A1 = *(const ulonglong2*)(sA + j * 4 + 256);
        const ulonglong2 A2 = *(const ulonglong2*)(sA + j * 4 + 512);
        const ulonglong2 A3 = *(const ulonglong2*)(sA + j * 4 + 768);
        const ulonglong2 B0 = *(const ulonglong2*)(sB + k * 4);
        const ulonglong2 B1 = *(const ulonglong2*)(sB + k * 4 + 256);
        const ulonglong2 B2 = *(const ulonglong2*)(sB + k * 4 + 512);
        const ulonglong2 B3 = *(const ulonglong2*)(sB + k * 4 + 768);

        #pragma unroll
        for (int p = 0; p < 2; ++p) {
            const u64 a0 = (p ? A0.y : A0.x) ^ sb2;    // sign + folds on A side
            const u64 a1 = (p ? A1.y : A1.x) ^ f1;
            const u64 a2 = (p ? A2.y : A2.x) ^ f1;
            const u64 a3 = (p ? A3.y : A3.x) ^ f3;
            const u64 b0 = p ? B0.y : B0.x;
            const u64 b1 = p ? B1.y : B1.x;
            const u64 b2 = p ? B2.y : B2.x;
            const u64 b3 = p ? B3.y : B3.x;
            const u64 b1f = b1 ^ neg2;                 // B variants for hi>=2
            const u64 b3f = b3 ^ neg2;

            u64 v00, v01, v02, v03, v10, v11, v12, v13;
            u64 v20, v21, v22, v23, v30, v31, v32, v33;
            MUL2(v00, a0, b0); MUL2(v01, a0, b1); MUL2(v02, a0, b2); MUL2(v03, a0, b3);
            MUL2(v10, a1, b0); MUL2(v11, a1, b1); MUL2(v12, a1, b2); MUL2(v13, a1, b3);
            MUL2(v20, a2, b0); MUL2(v21, a2, b1f); MUL2(v22, a2, b2); MUL2(v23, a2, b3f);
            MUL2(v30, a3, b0); MUL2(v31, a3, b1f); MUL2(v32, a3, b2); MUL2(v33, a3, b3f);

            // geometric: signed products -> plain ADD2 (rt2)
            ADD2(Gm[0][p], Gm[0][p], v00);
            ADD2(Gm[0][p], Gm[0][p], v11);
            ADD2(Gm[0][p], Gm[0][p], v22);
            ADD2(Gm[0][p], Gm[0][p], v33);
            ADD2(Gm[1][p], Gm[1][p], v01);
            ADD2(Gm[1][p], Gm[1][p], v10);
            ADD2(Gm[1][p], Gm[1][p], v23);
            ADD2(Gm[1][p], Gm[1][p], v32);
            ADD2(Gm[2][p], Gm[2][p], v02);
            ADD2(Gm[2][p], Gm[2][p], v13);
            ADD2(Gm[2][p], Gm[2][p], v20);
            ADD2(Gm[2][p], Gm[2][p], v31);
            ADD2(Gm[3][p], Gm[3][p], v03);
            ADD2(Gm[3][p], Gm[3][p], v12);
            ADD2(Gm[3][p], Gm[3][p], v21);
            ADD2(Gm[3][p], Gm[3][p], v30);
            // wedge: active iff hi & hv == 0 (high bits), low via w2 mask
            FMA2(Wm[0][p], v00, w2, Wm[0][p]);
            FMA2(Wm[1][p], v01, w2, Wm[1][p]);
            FMA2(Wm[1][p], v10, w2, Wm[1][p]);
            FMA2(Wm[2][p], v02, w2, Wm[2][p]);
            FMA2(Wm[2][p], v20, w2, Wm[2][p]);
            FMA2(Wm[3][p], v03, w2, Wm[3][p]);
            FMA2(Wm[3][p], v12, w2, Wm[3][p]);
            FMA2(Wm[3][p], v21, w2, Wm[3][p]);
            FMA2(Wm[3][p], v30, w2, Wm[3][p]);
            // inner: diagonal c1|c2; off-diag c1 (hi sub hv) or c2 (hv sub hi)
            FMA2(Nm[0][p], v00, n12, Nm[0][p]);
            FMA2(Nm[0][p], v11, n12, Nm[0][p]);
            FMA2(Nm[0][p], v22, n12, Nm[0][p]);
            FMA2(Nm[0][p], v33, n12, Nm[0][p]);
            FMA2(Nm[1][p], v01, n1, Nm[1][p]);
            FMA2(Nm[1][p], v23, n1, Nm[1][p]);
            FMA2(Nm[1][p], v10, n2, Nm[1][p]);
            FMA2(Nm[1][p], v32, n2, Nm[1][p]);
            FMA2(Nm[2][p], v02, n1, Nm[2][p]);
            FMA2(Nm[2][p], v13, n1, Nm[2][p]);
            FMA2(Nm[2][p], v20, n2, Nm[2][p]);
            FMA2(Nm[2][p], v31, n2, Nm[2][p]);
            FMA2(Nm[3][p], v03, n1, Nm[3][p]);
            FMA2(Nm[3][p], v30, n2, Nm[3][p]);
        }
    }

    // Tree reduction across the 4 j-slices (smem aliased over sA/sB)
    __syncthreads();
    u64* red = (u64*)smem_raw;

    if (tid >= 64) {                               // slices 2,3 store
        u64* dst = red + (tid - 64) * RSTRIDE;
        #pragma unroll
        for (int m = 0; m < 4; ++m)
            #pragma unroll
            for (int p = 0; p < 2; ++p) {
                dst[m * 2 + p] = Gm[m][p];
                dst[8 + m * 2 + p] = Wm[m][p];
                dst[16 + m * 2 + p] = Nm[m][p];
            }
    }
    __syncthreads();
    if (tid < 64) {                                // slices 0,1 add
        const u64* src = red + tid * RSTRIDE;
        #pragma unroll
        for (int m = 0; m < 4; ++m)
            #pragma unroll
            for (int p = 0; p < 2; ++p) {
                ADD2(Gm[m][p], Gm[m][p], src[m * 2 + p]);
                ADD2(Wm[m][p], Wm[m][p], src[8 + m * 2 + p]);
                ADD2(Nm[m][p], Nm[m][p], src[16 + m * 2 + p]);
            }
    }
    __syncthreads();
    if (tid >= 32 && tid < 64) {                   // slice 1 stores
        u64* dst = red + (tid - 32) * RSTRIDE;
        #pragma unroll
        for (int m = 0; m < 4; ++m)
            #pragma unroll
            for (int p = 0; p < 2; ++p) {
                dst[m * 2 + p] = Gm[m][p];
                dst[8 + m * 2 + p] = Wm[m][p];
                dst[16 + m * 2 + p] = Nm[m][p];
            }
    }
    __syncthreads();
    if (tid < 32) {                                // slice 0 adds + writes
        const u64* src = red + tid * RSTRIDE;
        #pragma unroll
        for (int m = 0; m < 4; ++m)
            #pragma unroll
            for (int p = 0; p < 2; ++p) {
                ADD2(Gm[m][p], Gm[m][p], src[m * 2 + p]);
                ADD2(Wm[m][p], Wm[m][p], src[8 + m * 2 + p]);
                ADD2(Nm[m][p], Nm[m][p], src[16 + m * 2 + p]);
            }
        #pragma unroll
        for (int m = 0; m < 4; ++m) {
            const int im = iL | (m << 6);
            #pragma unroll
            for (int p = 0; p < 2; ++p) {
                const int be0 = base + 2 * p;
                float2 g = unpack2(Gm[m][p]);
                float2 w = unpack2(Wm[m][p]);
                float2 n = unpack2(Nm[m][p]);
                out[(0 * BATCH_ELEMS + be0) * NCOMP + im] = g.x;
                out[(0 * BATCH_ELEMS + be0 + 1) * NCOMP + im] = g.y;
                out[(1 * BATCH_ELEMS + be0) * NCOMP + im] = w.x;
                out[(1 * BATCH_ELEMS + be0 + 1) * NCOMP + im] = w.y;
                out[(2 * BATCH_ELEMS + be0) * NCOMP + im] = n.x;
                out[(2 * BATCH_ELEMS + be0 + 1) * NCOMP + im] = n.y;
            }
        }
    }
}

extern "C" void kernel_launch(void* const* d_in, const int* in_sizes, int n_in,
                              void* d_out, int out_size) {
    const float* A = (const float*)d_in[0];
    const float* B = (const float*)d_in[1];
    float* out = (float*)d_out;
    clifford_kernel<<<(BATCH_ELEMS / G) * 2, 128>>>(A, B, out);
}

// round 15
// speedup vs baseline: 1.3708x; 1.3708x over previous
#include <cuda_runtime.h>
#include <stdint.h>

// Cl(8,0,0): 256 comps, 1024 multivectors (4x256), out [3,1024,256].
// 4x4 XOR tiling on bits 6,7 (R11/R12). R15: factored accumulation — sum
// products sharing a coefficient first, then one coefficient-FMA per tree:
// 45 FP2 per (u,p) instead of 55 (pure re-association, same values).
// G=4 batch elems, 128-thr blocks (32 iL x 4 j-slices), grid 512.

#define NCOMP 256
#define G 4
#define BATCH_ELEMS 1024

typedef unsigned long long u64;

#define MUL2(out, a, b) \
    asm("mul.rn.f32x2 %0, %1, %2;" : "=l"(out) : "l"(a), "l"(b))
#define FMA2(out, a, b, c) \
    asm("fma.rn.f32x2 %0, %1, %2, %3;" : "=l"(out) : "l"(a), "l"(b), "l"(c))
#define ADD2(out, a, b) \
    asm("add.rn.f32x2 %0, %1, %2;" : "=l"(out) : "l"(a), "l"(b))

__device__ __forceinline__ u64 pack2(unsigned w) {
    u64 r;
    asm("mov.b64 %0, {%1, %1};" : "=l"(r) : "r"(w));
    return r;
}
__device__ __forceinline__ float2 unpack2(u64 v) {
    float2 f;
    asm("mov.b64 {%0, %1}, %2;" : "=f"(f.x), "=f"(f.y) : "l"(v));
    return f;
}

__host__ __device__ __forceinline__ constexpr unsigned ppf(unsigned v) {
    unsigned x = v << 1;
    x ^= x << 1;
    x ^= x << 2;
    x ^= x << 4;
    return x & 0xffu;
}

__device__ __forceinline__ unsigned submask16(unsigned m) {
    unsigned w = 1u;
    if (m & 1u) w |= w << 1;
    if (m & 2u) w |= w << 2;
    if (m & 4u) w |= w << 4;
    if (m & 8u) w |= w << 8;
    return w;
}
__device__ __forceinline__ unsigned supmask16(unsigned r) {
    unsigned w = 0xFFFFu;
    if (r & 1u) w &= 0xAAAAu;
    if (r & 2u) w &= 0xCCCCu;
    if (r & 4u) w &= 0xF0F0u;
    if (r & 8u) w &= 0xFF00u;
    return w;
}

// smem: phase 1: sA (4096B) + sB (4096B); phase 2 (aliased): 64*25 u64 = 12800B
#define SMEM_BYTES 12800
#define RSTRIDE 25

__global__ __launch_bounds__(128, 4) void clifford_kernel(
    const float* __restrict__ A,
    const float* __restrict__ B,
    float* __restrict__ out) {
    __shared__ __align__(16) char smem_raw[SMEM_BYTES];
    float* sA = (float*)smem_raw;             // [j*4 + g], (-1)^q(j) folded in
    float* sB = (float*)(smem_raw + 4096);    // [k*4 + g], 16B rows

    const int tid = threadIdx.x;              // 0..127
    const int s = tid >> 5;                   // j-slice 0..3 (one per warp)
    const int iq = blockIdx.x & 1;
    const int iL = iq * 32 + (tid & 31);      // base i (bits 6,7 = 0)
    const int base = (blockIdx.x >> 1) * G;

    // Coalesced fill; fold (-1)^{q(j)} into A
    #pragma unroll
    for (int r = 0; r < (NCOMP * G) / 128; ++r) {
        int idx = r * 128 + tid;
        int j = idx & (NCOMP - 1);
        int g = idx >> 8;
        float a = A[(base + g) * NCOMP + j];
        unsigned q = (unsigned)__popc(j & (int)ppf((unsigned)j)) & 1u;
        sA[j * 4 + g] = __int_as_float(__float_as_int(a) ^ (int)(q << 31));
        sB[j * 4 + g] = B[(base + g) * NCOMP + j];
    }
    __syncthreads();

    const int i = iL;
    const unsigned pp_i = ppf((unsigned)i);
    const unsigned par_i = (unsigned)__popc(i) & 1u;
    const u64 pis2 = pack2(par_i << 31);
    const u64 neg2 = 0x8000000080000000ULL;

    unsigned lut_s = 0u;                      // bit u = parity(u & pp_i)
    if (pp_i & 1u) lut_s ^= 0xAAAAu;
    if (pp_i & 2u) lut_s ^= 0xCCCCu;
    if (pp_i & 4u) lut_s ^= 0xF0F0u;
    if (pp_i & 8u) lut_s ^= 0xFF00u;

    const int jo = s << 4;                    // bits 4,5 of j
    const unsigned pjo = (unsigned)__popc(jo & (int)pp_i) & 1u;
    const unsigned S_w = pjo ? (lut_s ^ 0xFFFFu) : lut_s;
    const unsigned W_w = (((jo & ~i) & 0x30) == 0) ? submask16((unsigned)i & 15u) : 0u;
    const unsigned C1_w = (((jo & i) & 0x30) == 0) ? submask16((unsigned)(~i) & 15u) : 0u;
    const unsigned C2_w = (((i & ~jo) & 0x30) == 0) ? supmask16((unsigned)i & 15u) : 0u;
    const int koi = jo ^ i;

    u64 Gm[4][2], Wm[4][2], Nm[4][2];
    #pragma unroll
    for (int m = 0; m < 4; ++m)
        #pragma unroll
        for (int p = 0; p < 2; ++p) { Gm[m][p] = 0ull; Wm[m][p] = 0ull; Nm[m][p] = 0ull; }

    #pragma unroll
    for (int u = 0; u < 16; ++u) {            // u compile-time
        const int j = jo | u;
        const int k = koi ^ u;
        const unsigned s32 = ((S_w << (31 - u)) & 0x80000000u) | 0x3f800000u;
        const unsigned wm = (unsigned)(((int)(W_w << (31 - u))) >> 31);
        const unsigned c1m = (unsigned)(((int)(C1_w << (31 - u))) >> 31);
        const unsigned c2m = (unsigned)(((int)(C2_w << (31 - u))) >> 31);
        const u64 s2 = pack2(s32);
        const u64 ws2 = pack2(s32 & wm);
        const u64 n1 = pack2(s32 & c1m);
        const u64 n2 = pack2(s32 & c2m);
        const u64 n12 = pack2(s32 & (c1m | c2m));

        const ulonglong2 A0 = *(const ulonglong2*)(sA + j * 4);
        const ulonglong2 A1 = *(const ulonglong2*)(sA + j * 4 + 256);
        const ulonglong2 A2 = *(const ulonglong2*)(sA + j * 4 + 512);
        const ulonglong2 A3 = *(const ulonglong2*)(sA + j * 4 + 768);
        const ulonglong2 B0 = *(const ulonglong2*)(sB + k * 4);
        const ulonglong2 B1 = *(const ulonglong2*)(sB + k * 4 + 256);
        const ulonglong2 B2 = *(const ulonglong2*)(sB + k * 4 + 512);
        const ulonglong2 B3 = *(const ulonglong2*)(sB + k * 4 + 768);

        #pragma unroll
        for (int p = 0; p < 2; ++p) {
            const u64 a0 = p ? A0.y : A0.x;
            const u64 a1 = (p ? A1.y : A1.x) ^ pis2;   // sign folds (A side)
            const u64 a2 = (p ? A2.y : A2.x) ^ pis2;
            const u64 a3 = (p ? A3.y : A3.x) ^ neg2;
            const u64 b0 = p ? B0.y : B0.x;
            const u64 b1 = p ? B1.y : B1.x;
            const u64 b2 = p ? B2.y : B2.x;
            const u64 b3 = p ? B3.y : B3.x;
            const u64 b1f = b1 ^ neg2;                 // B variants for hi>=2
            const u64 b3f = b3 ^ neg2;

            u64 v00, v01, v02, v03, v10, v11, v12, v13;
            u64 v20, v21, v22, v23, v30, v31, v32, v33;
            MUL2(v00, a0, b0); MUL2(v01, a0, b1); MUL2(v02, a0, b2); MUL2(v03, a0, b3);
            MUL2(v10, a1, b0); MUL2(v11, a1, b1); MUL2(v12, a1, b2); MUL2(v13, a1, b3);
            MUL2(v20, a2, b0); MUL2(v21, a2, b1f); MUL2(v22, a2, b2); MUL2(v23, a2, b3f);
            MUL2(v30, a3, b0); MUL2(v31, a3, b1f); MUL2(v32, a3, b2); MUL2(v33, a3, b3f);

            // ---- m=0 (diag): t0 = v00+v11+v22+v33 ----
            {
                u64 x, y, t0;
                ADD2(x, v00, v11);
                ADD2(y, v22, v33);
                ADD2(t0, x, y);
                FMA2(Gm[0][p], t0, s2, Gm[0][p]);
                FMA2(Nm[0][p], t0, n12, Nm[0][p]);
                FMA2(Wm[0][p], v00, ws2, Wm[0][p]);
            }
            // ---- m=1: subsums (v01+v23), (v10+v32); wedge (v01+v10) ----
            {
                u64 s1a, s1b, t1, wsum;
                ADD2(s1a, v01, v23);
                ADD2(s1b, v10, v32);
                ADD2(t1, s1a, s1b);
                ADD2(wsum, v01, v10);
                FMA2(Gm[1][p], t1, s2, Gm[1][p]);
                FMA2(Nm[1][p], s1a, n1, Nm[1][p]);
                FMA2(Nm[1][p], s1b, n2, Nm[1][p]);
                FMA2(Wm[1][p], wsum, ws2, Wm[1][p]);
            }
            // ---- m=2: subsums (v02+v13), (v20+v31); wedge (v02+v20) ----
            {
                u64 s2a, s2b, t2, wsum;
                ADD2(s2a, v02, v13);
                ADD2(s2b, v20, v31);
                ADD2(t2, s2a, s2b);
                ADD2(wsum, v02, v20);
                FMA2(Gm[2][p], t2, s2, Gm[2][p]);
                FMA2(Nm[2][p], s2a, n1, Nm[2][p]);
                FMA2(Nm[2][p], s2b, n2, Nm[2][p]);
                FMA2(Wm[2][p], wsum, ws2, Wm[2][p]);
            }
            // ---- m=3: t3 = all four; wedge uses t3; inner v03, v30 only ----
            {
                u64 x, y, t3;
                ADD2(x, v03, v12);
                ADD2(y, v21, v30);
                ADD2(t3, x, y);
                FMA2(Gm[3][p], t3, s2, Gm[3][p]);
                FMA2(Wm[3][p], t3, ws2, Wm[3][p]);
                FMA2(Nm[3][p], v03, n1, Nm[3][p]);
                FMA2(Nm[3][p], v30, n2, Nm[3][p]);
            }
        }
    }

    // Tree reduction across the 4 j-slices (smem aliased over sA/sB)
    __syncthreads();
    u64* red = (u64*)smem_raw;

    if (tid >= 64) {                               // slices 2,3 store
        u64* dst = red + (tid - 64) * RSTRIDE;
        #pragma unroll
        for (int m = 0; m < 4; ++m)
            #pragma unroll
            for (int p = 0; p < 2; ++p) {
                dst[m * 2 + p] = Gm[m][p];
                dst[8 + m * 2 + p] = Wm[m][p];
                dst[16 + m * 2 + p] = Nm[m][p];
            }
    }
    __syncthreads();
    if (tid < 64) {                                // slices 0,1 add
        const u64* src = red + tid * RSTRIDE;
        #pragma unroll
        for (int m = 0; m < 4; ++m)
            #pragma unroll
            for (int p = 0; p < 2; ++p) {
                ADD2(Gm[m][p], Gm[m][p], src[m * 2 + p]);
                ADD2(Wm[m][p], Wm[m][p], src[8 + m * 2 + p]);
                ADD2(Nm[m][p], Nm[m][p], src[16 + m * 2 + p]);
            }
    }
    __syncthreads();
    if (tid >= 32 && tid < 64) {                   // slice 1 stores
        u64* dst = red + (tid - 32) * RSTRIDE;
        #pragma unroll
        for (int m = 0; m < 4; ++m)
            #pragma unroll
            for (int p = 0; p < 2; ++p) {
                dst[m * 2 + p] = Gm[m][p];
                dst[8 + m * 2 + p] = Wm[m][p];
                dst[16 + m * 2 + p] = Nm[m][p];
            }
    }
    __syncthreads();
    if (tid < 32) {                                // slice 0 adds + writes
        const u64* src = red + tid * RSTRIDE;
        #pragma unroll
        for (int m = 0; m < 4; ++m)
            #pragma unroll
            for (int p = 0; p < 2; ++p) {
                ADD2(Gm[m][p], Gm[m][p], src[m * 2 + p]);
                ADD2(Wm[m][p], Wm[m][p], src[8 + m * 2 + p]);
                ADD2(Nm[m][p], Nm[m][p], src[16 + m * 2 + p]);
            }
        #pragma unroll
        for (int m = 0; m < 4; ++m) {
            const int im = iL | (m << 6);
            #pragma unroll
            for (int p = 0; p < 2; ++p) {
                const int be0 = base + 2 * p;
                float2 g = unpack2(Gm[m][p]);
                float2 w = unpack2(Wm[m][p]);
                float2 n = unpack2(Nm[m][p]);
                out[(0 * BATCH_ELEMS + be0) * NCOMP + im] = g.x;
                out[(0 * BATCH_ELEMS + be0 + 1) * NCOMP + im] = g.y;
                out[(1 * BATCH_ELEMS + be0) * NCOMP + im] = w.x;
                out[(1 * BATCH_ELEMS + be0 + 1) * NCOMP + im] = w.y;
                out[(2 * BATCH_ELEMS + be0) * NCOMP + im] = n.x;
                out[(2 * BATCH_ELEMS + be0 + 1) * NCOMP + im] = n.y;
            }
        }
    }
}

extern "C" void kernel_launch(void* const* d_in, const int* in_sizes, int n_in,
                              void* d_out, int out_size) {
    const float* A = (const float*)d_in[0];
    const float* B = (const float*)d_in[1];
    float* out = (float*)d_out;
    clifford_kernel<<<(BATCH_ELEMS / G) * 2, 128>>>(A, B, out);
}